// round 3
// baseline (speedup 1.0000x reference)
#include <cuda_runtime.h>
#include <cuda_bf16.h>
#include <math.h>

#define L_ 1024
#define B_ 24
#define D_ 512
#define TD 1536

// ---------------- scratch (device globals; no runtime allocation) -----------
__device__ float g_ta[(size_t)L_*B_*D_];      // tanh(v @ Wp^T)
__device__ float g_tb[(size_t)L_*B_*D_];      // tanh(v @ Wp_^T)
__device__ float g_S [(size_t)L_*B_*L_];      // scores -> softmax weights
__device__ float g_c [(size_t)L_*B_*D_];      // contexts
__device__ float g_gi[(size_t)L_*B_*TD];      // c @ w_ih^T + b_ih
__device__ unsigned g_bar;

// ---------------- generic fp32 SGEMM: C = A * op(B) (+bias)(tanh) -----------
// A: [M,K] row-major, lda. TRANSB: B is [N,K] row-major (NT). else B is [K,N].
// BM=BN=64, BK=16, 256 threads, 4x4 micro.
template<bool TRANSB, bool BIAS, bool TANH>
__global__ __launch_bounds__(256)
void sgemm(const float* __restrict__ A, long lda, long sAz,
           const float* __restrict__ Bm, long ldb, long sBz,
           const float* __restrict__ bias,
           float* __restrict__ C, long ldc, long sCz,
           int M, int N, int K)
{
    __shared__ float As[16][68];
    __shared__ float Bs[16][68];

    const int tid = threadIdx.x;
    const int tx = tid & 15, ty = tid >> 4;
    const int m0 = blockIdx.y * 64, n0 = blockIdx.x * 64;
    const int z = blockIdx.z;
    A  += (size_t)z * sAz;
    Bm += (size_t)z * sBz;
    C  += (size_t)z * sCz;

    const int ar = tid >> 2, ac = (tid & 3) * 4;   // A tile: row 0..63, k-off
    // B tile mapping
    const int br = tid >> 2, bc = (tid & 3) * 4;   // NT: n-row, k-off
    const int bk = tid >> 4, bn = (tid & 15) * 4;  // NN: k-row, n-off

    float acc[4][4];
    #pragma unroll
    for (int i = 0; i < 4; i++)
        #pragma unroll
        for (int j = 0; j < 4; j++) acc[i][j] = 0.f;

    const int nk = K / 16;
    float4 rA = *(const float4*)&A[(size_t)(m0 + ar) * lda + ac];
    float4 rB;
    if (TRANSB) rB = *(const float4*)&Bm[(size_t)(n0 + br) * ldb + bc];
    else        rB = *(const float4*)&Bm[(size_t)bk * ldb + n0 + bn];

    for (int t = 0; t < nk; ++t) {
        As[ac+0][ar] = rA.x; As[ac+1][ar] = rA.y; As[ac+2][ar] = rA.z; As[ac+3][ar] = rA.w;
        if (TRANSB) {
            Bs[bc+0][br] = rB.x; Bs[bc+1][br] = rB.y; Bs[bc+2][br] = rB.z; Bs[bc+3][br] = rB.w;
        } else {
            *(float4*)&Bs[bk][bn] = rB;
        }
        __syncthreads();
        if (t + 1 < nk) {
            int k0 = (t + 1) * 16;
            rA = *(const float4*)&A[(size_t)(m0 + ar) * lda + k0 + ac];
            if (TRANSB) rB = *(const float4*)&Bm[(size_t)(n0 + br) * ldb + k0 + bc];
            else        rB = *(const float4*)&Bm[(size_t)(k0 + bk) * ldb + n0 + bn];
        }
        #pragma unroll
        for (int k = 0; k < 16; ++k) {
            float4 a = *(const float4*)&As[k][ty * 4];
            float4 b = *(const float4*)&Bs[k][tx * 4];
            float av[4] = {a.x, a.y, a.z, a.w};
            float bv[4] = {b.x, b.y, b.z, b.w};
            #pragma unroll
            for (int i = 0; i < 4; i++)
                #pragma unroll
                for (int j = 0; j < 4; j++)
                    acc[i][j] = fmaf(av[i], bv[j], acc[i][j]);
        }
        __syncthreads();
    }

    #pragma unroll
    for (int i = 0; i < 4; i++) {
        float4 o;
        float* op = (float*)&o;
        #pragma unroll
        for (int j = 0; j < 4; j++) {
            float v = acc[i][j];
            if (BIAS) v += bias[n0 + tx * 4 + j];
            if (TANH) v = tanhf(v);
            op[j] = v;
        }
        *(float4*)&C[(size_t)(m0 + ty * 4 + i) * ldc + n0 + tx * 4] = o;
    }
}

// ---------------- scores: S[i,b,l] = sum_h V[b,h]*(ta+tb)/(1+ta*tb) ---------
__global__ __launch_bounds__(256)
void scores_k(const float* __restrict__ ta, const float* __restrict__ tb,
              const float* __restrict__ V, float* __restrict__ S)
{
    __shared__ float Ta[16][68];
    __shared__ float Tb[16][68];
    __shared__ float Vs[16];

    const int tid = threadIdx.x;
    const int tx = tid & 15, ty = tid >> 4;
    const int l0 = blockIdx.x * 64, i0 = blockIdx.y * 64, b = blockIdx.z;
    const int ar = tid >> 2, ac = (tid & 3) * 4;

    float acc[4][4];
    #pragma unroll
    for (int i = 0; i < 4; i++)
        #pragma unroll
        for (int j = 0; j < 4; j++) acc[i][j] = 0.f;

    for (int k0 = 0; k0 < D_; k0 += 16) {
        __syncthreads();
        {
            float4 fa = *(const float4*)&ta[((size_t)(i0 + ar) * B_ + b) * D_ + k0 + ac];
            float4 fb = *(const float4*)&tb[((size_t)(l0 + ar) * B_ + b) * D_ + k0 + ac];
            Ta[ac+0][ar] = fa.x; Ta[ac+1][ar] = fa.y; Ta[ac+2][ar] = fa.z; Ta[ac+3][ar] = fa.w;
            Tb[ac+0][ar] = fb.x; Tb[ac+1][ar] = fb.y; Tb[ac+2][ar] = fb.z; Tb[ac+3][ar] = fb.w;
            if (tid < 16) Vs[tid] = V[(size_t)b * D_ + k0 + tid];
        }
        __syncthreads();
        #pragma unroll
        for (int k = 0; k < 16; ++k) {
            float4 a = *(const float4*)&Ta[k][ty * 4];
            float4 bb = *(const float4*)&Tb[k][tx * 4];
            float av[4] = {a.x, a.y, a.z, a.w};
            float bv[4] = {bb.x, bb.y, bb.z, bb.w};
            float vk = Vs[k];
            #pragma unroll
            for (int i = 0; i < 4; i++)
                #pragma unroll
                for (int j = 0; j < 4; j++) {
                    float num = av[i] + bv[j];
                    float den = fmaf(av[i], bv[j], 1.0f);
                    float x = __fdividef(num, den);   // exact tanh-sum identity
                    acc[i][j] = fmaf(vk, x, acc[i][j]);
                }
        }
    }

    #pragma unroll
    for (int i = 0; i < 4; i++) {
        float4 o = {acc[i][0], acc[i][1], acc[i][2], acc[i][3]};
        *(float4*)&S[((size_t)(i0 + ty * 4 + i) * B_ + b) * (size_t)L_ + l0 + tx * 4] = o;
    }
}

// ---------------- row softmax over 1024 ------------------------------------
__global__ __launch_bounds__(256)
void softmax_k(float* __restrict__ S)
{
    __shared__ float redm[8];
    __shared__ float reds[8];
    const size_t row = blockIdx.x;
    float* p = S + row * (size_t)L_;
    const int t = threadIdx.x, lane = t & 31, wid = t >> 5;

    float4 x = *(float4*)&p[t * 4];
    float m = fmaxf(fmaxf(x.x, x.y), fmaxf(x.z, x.w));
    #pragma unroll
    for (int o = 16; o; o >>= 1) m = fmaxf(m, __shfl_xor_sync(~0u, m, o));
    if (lane == 0) redm[wid] = m;
    __syncthreads();
    if (wid == 0) {
        float mm = (lane < 8) ? redm[lane] : -1e30f;
        #pragma unroll
        for (int o = 4; o; o >>= 1) mm = fmaxf(mm, __shfl_xor_sync(~0u, mm, o));
        if (lane == 0) redm[0] = mm;
    }
    __syncthreads();
    m = redm[0];

    float4 e;
    e.x = __expf(x.x - m); e.y = __expf(x.y - m);
    e.z = __expf(x.z - m); e.w = __expf(x.w - m);
    float s = e.x + e.y + e.z + e.w;
    #pragma unroll
    for (int o = 16; o; o >>= 1) s += __shfl_xor_sync(~0u, s, o);
    if (lane == 0) reds[wid] = s;
    __syncthreads();
    if (wid == 0) {
        float ss = (lane < 8) ? reds[lane] : 0.f;
        #pragma unroll
        for (int o = 4; o; o >>= 1) ss += __shfl_xor_sync(~0u, ss, o);
        if (lane == 0) reds[0] = ss;
    }
    __syncthreads();
    float inv = __fdividef(1.0f, reds[0]);
    e.x *= inv; e.y *= inv; e.z *= inv; e.w *= inv;
    *(float4*)&p[t * 4] = e;
}

// ---------------- recurrence ------------------------------------------------
#define RCTA 128
#define RTHR 128
#define HP   516   // padded row pitch (floats), 16B-aligned, bank-staggered

__global__ void reset_bar() { g_bar = 0; }

__global__ __launch_bounds__(RTHR)
void gru_k(const float* __restrict__ h0, const float* __restrict__ gi,
           const float* __restrict__ w_hh, const float* __restrict__ b_hh,
           float* __restrict__ out)
{
    extern __shared__ float sm[];
    float* h_s  = sm;                 // [B_][HP]
    float* w_s  = sm + B_ * HP;       // [12][HP]
    float* gh_p = w_s + 12 * HP;      // [4][12][B_]

    const int c = blockIdx.x, t = threadIdx.x;

    // load this CTA's 12 w_hh rows: gate g, d = c*4 + do  -> j = g*4+do
    for (int idx = t; idx < 12 * 128; idx += RTHR) {
        int j = idx >> 7, kk = (idx & 127) * 4;
        int row = (j >> 2) * D_ + c * 4 + (j & 3);
        *(float4*)&w_s[j * HP + kk] = *(const float4*)&w_hh[(size_t)row * D_ + kk];
    }
    __syncthreads();

    // compute-thread mapping (t < 96): kq 0..3, nq 0..3 (3 j-rows), bq 0..5 (4 b)
    const int kq = t / 24, rem = t % 24, nq = rem / 6, bq = rem % 6;
    const int b0 = bq * 4, j0 = nq * 3, kbase = kq * 128;
    // gate-thread mapping (t < 96): b, dq
    const int gb = t % 24, gdq = t / 24;
    const int gd = c * 4 + gdq;

    for (int i = 0; i < L_; ++i) {
        const float* hp = (i == 0) ? h0 : out + (size_t)(i - 1) * B_ * D_;
        for (int idx = t; idx < B_ * 128; idx += RTHR) {
            int b = idx >> 7, kk = (idx & 127) * 4;
            *(float4*)&h_s[b * HP + kk] = *(const float4*)&hp[(size_t)b * D_ + kk];
        }
        __syncthreads();

        if (t < 96) {
            float a0[4], a1[4], a2[4];
            #pragma unroll
            for (int r = 0; r < 4; r++) { a0[r] = 0.f; a1[r] = 0.f; a2[r] = 0.f; }
            for (int kk = kbase; kk < kbase + 128; kk += 4) {
                float4 w0 = *(const float4*)&w_s[(j0 + 0) * HP + kk];
                float4 w1 = *(const float4*)&w_s[(j0 + 1) * HP + kk];
                float4 w2 = *(const float4*)&w_s[(j0 + 2) * HP + kk];
                #pragma unroll
                for (int r = 0; r < 4; r++) {
                    float4 hv = *(const float4*)&h_s[(b0 + r) * HP + kk];
                    a0[r] = fmaf(hv.x, w0.x, a0[r]); a0[r] = fmaf(hv.y, w0.y, a0[r]);
                    a0[r] = fmaf(hv.z, w0.z, a0[r]); a0[r] = fmaf(hv.w, w0.w, a0[r]);
                    a1[r] = fmaf(hv.x, w1.x, a1[r]); a1[r] = fmaf(hv.y, w1.y, a1[r]);
                    a1[r] = fmaf(hv.z, w1.z, a1[r]); a1[r] = fmaf(hv.w, w1.w, a1[r]);
                    a2[r] = fmaf(hv.x, w2.x, a2[r]); a2[r] = fmaf(hv.y, w2.y, a2[r]);
                    a2[r] = fmaf(hv.z, w2.z, a2[r]); a2[r] = fmaf(hv.w, w2.w, a2[r]);
                }
            }
            #pragma unroll
            for (int r = 0; r < 4; r++) {
                gh_p[(kq * 12 + j0 + 0) * B_ + b0 + r] = a0[r];
                gh_p[(kq * 12 + j0 + 1) * B_ + b0 + r] = a1[r];
                gh_p[(kq * 12 + j0 + 2) * B_ + b0 + r] = a2[r];
            }
        }
        __syncthreads();

        if (t < 96) {
            float ghr = 0.f, ghz = 0.f, ghn = 0.f;
            #pragma unroll
            for (int q = 0; q < 4; q++) {
                ghr += gh_p[(q * 12 + 0 + gdq) * B_ + gb];
                ghz += gh_p[(q * 12 + 4 + gdq) * B_ + gb];
                ghn += gh_p[(q * 12 + 8 + gdq) * B_ + gb];
            }
            size_t girow = ((size_t)i * B_ + gb) * TD;
            float ir = gi[girow + gd];
            float iz = gi[girow + D_ + gd];
            float in = gi[girow + 2 * D_ + gd];
            float hr = ghr + b_hh[gd];
            float hz = ghz + b_hh[D_ + gd];
            float hn = ghn + b_hh[2 * D_ + gd];
            float r = __fdividef(1.0f, 1.0f + __expf(-(ir + hr)));
            float z = __fdividef(1.0f, 1.0f + __expf(-(iz + hz)));
            float n = tanhf(in + r * hn);
            float hprev = h_s[gb * HP + gd];
            float hnew = (1.0f - z) * n + z * hprev;
            out[((size_t)i * B_ + gb) * D_ + gd] = hnew;
        }

        // global step barrier (monotonic counter, reset by reset_bar each launch)
        __threadfence();
        __syncthreads();
        if (t == 0) {
            atomicAdd(&g_bar, 1u);
            unsigned tgt = (unsigned)(i + 1) * gridDim.x;
            while (*((volatile unsigned*)&g_bar) < tgt) { }
        }
        __syncthreads();
        __threadfence();
    }
}

// ---------------- launch -----------------------------------------------------
extern "C" void kernel_launch(void* const* d_in, const int* in_sizes, int n_in,
                              void* d_out, int out_size)
{
    const float* v    = (const float*)d_in[0];
    const float* h0   = (const float*)d_in[1];
    const float* V    = (const float*)d_in[2];
    const float* Wp   = (const float*)d_in[3];
    const float* Wp_  = (const float*)d_in[4];
    const float* w_ih = (const float*)d_in[5];
    const float* w_hh = (const float*)d_in[6];
    const float* b_ih = (const float*)d_in[7];
    const float* b_hh = (const float*)d_in[8];
    float* out = (float*)d_out;

    float *ta, *tb, *S, *c, *gi;
    cudaGetSymbolAddress((void**)&ta, g_ta);
    cudaGetSymbolAddress((void**)&tb, g_tb);
    cudaGetSymbolAddress((void**)&S,  g_S);
    cudaGetSymbolAddress((void**)&c,  g_c);
    cudaGetSymbolAddress((void**)&gi, g_gi);

    const int smem_gru = (B_ * HP + 12 * HP + 4 * 12 * B_) * 4;
    cudaFuncSetAttribute(gru_k, cudaFuncAttributeMaxDynamicSharedMemorySize, smem_gru);

    // 1,2: projections with tanh epilogue
    sgemm<true, false, true><<<dim3(D_ / 64, (L_ * B_) / 64, 1), 256>>>(
        v, D_, 0, Wp, D_, 0, nullptr, ta, D_, 0, L_ * B_, D_, D_);
    sgemm<true, false, true><<<dim3(D_ / 64, (L_ * B_) / 64, 1), 256>>>(
        v, D_, 0, Wp_, D_, 0, nullptr, tb, D_, 0, L_ * B_, D_, D_);

    // 3: attention scores
    scores_k<<<dim3(L_ / 64, L_ / 64, B_), 256>>>(ta, tb, V, S);

    // 4: softmax over l
    softmax_k<<<L_ * B_, 256>>>(S);

    // 5: context c[i,b,:] = sum_l a[i,b,l] * v[l,b,:]  (per-b NN GEMM)
    sgemm<false, false, false><<<dim3(D_ / 64, L_ / 64, B_), 256>>>(
        S, (long)B_ * L_, L_,
        v, (long)B_ * D_, D_,
        nullptr,
        c, (long)B_ * D_, D_,
        L_, D_, L_);

    // 6: gi = c @ w_ih^T + b_ih
    sgemm<true, true, false><<<dim3(TD / 64, (L_ * B_) / 64, 1), 256>>>(
        c, D_, 0, w_ih, D_, 0, b_ih, gi, TD, 0, L_ * B_, TD, D_);

    // 7: recurrence
    reset_bar<<<1, 1>>>();
    gru_k<<<RCTA, RTHR, smem_gru>>>(h0, gi, w_hh, b_hh, out);
}

// round 4
// speedup vs baseline: 1.0263x; 1.0263x over previous
#include <cuda_runtime.h>
#include <cuda_bf16.h>
#include <math.h>

#define L_ 1024
#define B_ 24
#define D_ 512
#define TD 1536

// ---------------- scratch (device globals; no runtime allocation) -----------
__device__ float g_ta[(size_t)L_*B_*D_];      // tanh(v @ Wp^T)
__device__ float g_tb[(size_t)L_*B_*D_];      // tanh(v @ Wp_^T)
__device__ float g_S [(size_t)L_*B_*L_];      // scores -> softmax weights
__device__ float g_c [(size_t)L_*B_*D_];      // contexts
__device__ float g_gi[(size_t)L_*B_*TD];      // c @ w_ih^T + b_ih
__device__ unsigned g_bar;

// ---------------- f32x2 helpers (exact IEEE fp32, pairwise) ------------------
__device__ __forceinline__ unsigned long long pk2(float lo, float hi) {
    unsigned long long r;
    asm("mov.b64 %0,{%1,%2};" : "=l"(r) : "f"(lo), "f"(hi));
    return r;
}
__device__ __forceinline__ float2 up2(unsigned long long a) {
    float2 f;
    asm("mov.b64 {%0,%1},%2;" : "=f"(f.x), "=f"(f.y) : "l"(a));
    return f;
}
__device__ __forceinline__ unsigned long long fma2(unsigned long long a,
                                                   unsigned long long b,
                                                   unsigned long long c) {
    unsigned long long d;
    asm("fma.rn.f32x2 %0,%1,%2,%3;" : "=l"(d) : "l"(a), "l"(b), "l"(c));
    return d;
}
__device__ __forceinline__ unsigned long long add2(unsigned long long a,
                                                   unsigned long long b) {
    unsigned long long d;
    asm("add.rn.f32x2 %0,%1,%2;" : "=l"(d) : "l"(a), "l"(b));
    return d;
}
__device__ __forceinline__ unsigned long long mul2(unsigned long long a,
                                                   unsigned long long b) {
    unsigned long long d;
    asm("mul.rn.f32x2 %0,%1,%2;" : "=l"(d) : "l"(a), "l"(b));
    return d;
}
__device__ __forceinline__ float rcpa(float x) {
    float r;
    asm("rcp.approx.f32 %0,%1;" : "=f"(r) : "f"(x));
    return r;
}

// ---------------- SGEMM v2: C = A * op(B) (+bias)(tanh), f32x2 --------------
// A: [M,K] row-major. TRANSB: B is [N,K] row-major (NT), else [K,N] (NN).
// BM=BN=128, BK=16, 256 threads, 8x8 micro (as 8x4 f32x2 pairs), dbl-buffered.
#define GBM 128
#define GBK 16

template<bool TRANSB, bool BIAS, bool TANH>
__global__ __launch_bounds__(256)
void sgemm2(const float* __restrict__ A, long lda, long sAz,
            const float* __restrict__ Bm, long ldb, long sBz,
            const float* __restrict__ bias,
            float* __restrict__ C, long ldc, long sCz, int K)
{
    __shared__ float As[2][GBK][GBM + 4];
    __shared__ float Bs[2][GBK][GBM + 4];

    const int tid = threadIdx.x;
    const int tx = tid & 15, ty = tid >> 4;
    const int n0 = blockIdx.x * GBM, m0 = blockIdx.y * GBM, z = blockIdx.z;
    A  += (size_t)z * sAz;
    Bm += (size_t)z * sBz;
    C  += (size_t)z * sCz;

    // A tile load mapping: 512 float4s, 2 per thread (transposed store)
    const int ar0 = tid >> 2, ar1 = (tid + 256) >> 2;
    const int akc = (tid & 3) * 4;
    const float* pA0 = A + (size_t)(m0 + ar0) * lda + akc;
    const float* pA1 = A + (size_t)(m0 + ar1) * lda + akc;

    // B tile mapping
    const float *pB0, *pB1;
    int bkr0 = 0, bkr1 = 0, bnc = 0;
    if (TRANSB) {
        pB0 = Bm + (size_t)(n0 + ar0) * ldb + akc;
        pB1 = Bm + (size_t)(n0 + ar1) * ldb + akc;
    } else {
        bkr0 = tid >> 5; bkr1 = bkr0 + 8; bnc = (tid & 31) * 4;
        pB0 = Bm + (size_t)bkr0 * ldb + n0 + bnc;
        pB1 = Bm + (size_t)bkr1 * ldb + n0 + bnc;
    }

    float4 ra0 = *(const float4*)pA0;
    float4 ra1 = *(const float4*)pA1;
    float4 rb0 = *(const float4*)pB0;
    float4 rb1 = *(const float4*)pB1;

    unsigned long long acc[8][4];
    #pragma unroll
    for (int i = 0; i < 8; i++)
        #pragma unroll
        for (int j = 0; j < 4; j++) acc[i][j] = 0ull;

    const int nk = K / GBK;

    // initial STS into buffer 0
    {
        As[0][akc+0][ar0] = ra0.x; As[0][akc+1][ar0] = ra0.y;
        As[0][akc+2][ar0] = ra0.z; As[0][akc+3][ar0] = ra0.w;
        As[0][akc+0][ar1] = ra1.x; As[0][akc+1][ar1] = ra1.y;
        As[0][akc+2][ar1] = ra1.z; As[0][akc+3][ar1] = ra1.w;
        if (TRANSB) {
            Bs[0][akc+0][ar0] = rb0.x; Bs[0][akc+1][ar0] = rb0.y;
            Bs[0][akc+2][ar0] = rb0.z; Bs[0][akc+3][ar0] = rb0.w;
            Bs[0][akc+0][ar1] = rb1.x; Bs[0][akc+1][ar1] = rb1.y;
            Bs[0][akc+2][ar1] = rb1.z; Bs[0][akc+3][ar1] = rb1.w;
        } else {
            *(float4*)&Bs[0][bkr0][bnc] = rb0;
            *(float4*)&Bs[0][bkr1][bnc] = rb1;
        }
    }
    __syncthreads();

    for (int t = 0; t < nk; ++t) {
        const int cb = t & 1;
        if (t + 1 < nk) {
            pA0 += GBK; pA1 += GBK;
            ra0 = *(const float4*)pA0;
            ra1 = *(const float4*)pA1;
            if (TRANSB) { pB0 += GBK; pB1 += GBK; }
            else        { pB0 += (size_t)GBK * ldb; pB1 += (size_t)GBK * ldb; }
            rb0 = *(const float4*)pB0;
            rb1 = *(const float4*)pB1;
        }

        #pragma unroll
        for (int k = 0; k < GBK; ++k) {
            float4 af0 = *(const float4*)&As[cb][k][ty * 4];
            float4 af1 = *(const float4*)&As[cb][k][ty * 4 + 64];
            ulonglong2 bq0 = *(const ulonglong2*)&Bs[cb][k][tx * 4];
            ulonglong2 bq1 = *(const ulonglong2*)&Bs[cb][k][tx * 4 + 64];
            unsigned long long bp[4] = {bq0.x, bq0.y, bq1.x, bq1.y};
            unsigned long long ad[8];
            ad[0] = pk2(af0.x, af0.x); ad[1] = pk2(af0.y, af0.y);
            ad[2] = pk2(af0.z, af0.z); ad[3] = pk2(af0.w, af0.w);
            ad[4] = pk2(af1.x, af1.x); ad[5] = pk2(af1.y, af1.y);
            ad[6] = pk2(af1.z, af1.z); ad[7] = pk2(af1.w, af1.w);
            #pragma unroll
            for (int i = 0; i < 8; i++)
                #pragma unroll
                for (int jp = 0; jp < 4; jp++)
                    acc[i][jp] = fma2(ad[i], bp[jp], acc[i][jp]);
        }

        if (t + 1 < nk) {
            const int nb = (t + 1) & 1;
            As[nb][akc+0][ar0] = ra0.x; As[nb][akc+1][ar0] = ra0.y;
            As[nb][akc+2][ar0] = ra0.z; As[nb][akc+3][ar0] = ra0.w;
            As[nb][akc+0][ar1] = ra1.x; As[nb][akc+1][ar1] = ra1.y;
            As[nb][akc+2][ar1] = ra1.z; As[nb][akc+3][ar1] = ra1.w;
            if (TRANSB) {
                Bs[nb][akc+0][ar0] = rb0.x; Bs[nb][akc+1][ar0] = rb0.y;
                Bs[nb][akc+2][ar0] = rb0.z; Bs[nb][akc+3][ar0] = rb0.w;
                Bs[nb][akc+0][ar1] = rb1.x; Bs[nb][akc+1][ar1] = rb1.y;
                Bs[nb][akc+2][ar1] = rb1.z; Bs[nb][akc+3][ar1] = rb1.w;
            } else {
                *(float4*)&Bs[nb][bkr0][bnc] = rb0;
                *(float4*)&Bs[nb][bkr1][bnc] = rb1;
            }
        }
        __syncthreads();
    }

    // epilogue
    #pragma unroll
    for (int i = 0; i < 8; i++) {
        const int m = m0 + ((i < 4) ? (ty * 4 + i) : (64 + ty * 4 + i - 4));
        float2 c0 = up2(acc[i][0]), c1 = up2(acc[i][1]);
        float2 c2 = up2(acc[i][2]), c3 = up2(acc[i][3]);
        float o0[4] = {c0.x, c0.y, c1.x, c1.y};
        float o1[4] = {c2.x, c2.y, c3.x, c3.y};
        #pragma unroll
        for (int j = 0; j < 4; j++) {
            if (BIAS) {
                o0[j] += bias[n0 + tx * 4 + j];
                o1[j] += bias[n0 + 64 + tx * 4 + j];
            }
            if (TANH) { o0[j] = tanhf(o0[j]); o1[j] = tanhf(o1[j]); }
        }
        *(float4*)&C[(size_t)m * ldc + n0 + tx * 4]      = *(float4*)o0;
        *(float4*)&C[(size_t)m * ldc + n0 + 64 + tx * 4] = *(float4*)o1;
    }
}

// ---------------- scores: S[i,b,l] = sum_h V[b,h]*(ta+tb)/(1+ta*tb) ---------
__global__ __launch_bounds__(256)
void scores_k(const float* __restrict__ ta, const float* __restrict__ tb,
              const float* __restrict__ V, float* __restrict__ S)
{
    __shared__ float Ta[16][68];
    __shared__ float Tb[16][68];
    __shared__ float Vs[16];

    const int tid = threadIdx.x;
    const int tx = tid & 15, ty = tid >> 4;
    const int l0 = blockIdx.x * 64, i0 = blockIdx.y * 64, b = blockIdx.z;
    const int ar = tid >> 2, ac = (tid & 3) * 4;

    unsigned long long acc[4][2];
    #pragma unroll
    for (int i = 0; i < 4; i++) { acc[i][0] = 0ull; acc[i][1] = 0ull; }

    for (int k0 = 0; k0 < D_; k0 += 16) {
        __syncthreads();
        {
            float4 fa = *(const float4*)&ta[((size_t)(i0 + ar) * B_ + b) * D_ + k0 + ac];
            float4 fb = *(const float4*)&tb[((size_t)(l0 + ar) * B_ + b) * D_ + k0 + ac];
            Ta[ac+0][ar] = fa.x; Ta[ac+1][ar] = fa.y; Ta[ac+2][ar] = fa.z; Ta[ac+3][ar] = fa.w;
            Tb[ac+0][ar] = fb.x; Tb[ac+1][ar] = fb.y; Tb[ac+2][ar] = fb.z; Tb[ac+3][ar] = fb.w;
            if (tid < 16) Vs[tid] = V[(size_t)b * D_ + k0 + tid];
        }
        __syncthreads();
        #pragma unroll
        for (int k = 0; k < 16; ++k) {
            float4 a  = *(const float4*)&Ta[k][ty * 4];
            float4 bb = *(const float4*)&Tb[k][tx * 4];
            ulonglong2 bq = *(const ulonglong2*)&Tb[k][tx * 4];
            const unsigned long long bp[2] = {bq.x, bq.y};
            const float av[4] = {a.x, a.y, a.z, a.w};
            const float bs0[2] = {bb.x, bb.z};
            const float bs1[2] = {bb.y, bb.w};
            const float vk = Vs[k];
            const unsigned long long vd = pk2(vk, vk);
            #pragma unroll
            for (int i = 0; i < 4; i++) {
                const unsigned long long ad = pk2(av[i], av[i]);
                #pragma unroll
                for (int jp = 0; jp < 2; jp++) {
                    // exact identity: tanh(a+b) = (ta+tb)/(1+ta*tb)
                    float d0 = fmaf(av[i], bs0[jp], 1.0f);
                    float d1 = fmaf(av[i], bs1[jp], 1.0f);
                    unsigned long long rp  = pk2(rcpa(d0), rcpa(d1));
                    unsigned long long num = add2(ad, bp[jp]);
                    unsigned long long x   = mul2(num, rp);
                    acc[i][jp] = fma2(vd, x, acc[i][jp]);
                }
            }
        }
    }

    #pragma unroll
    for (int i = 0; i < 4; i++) {
        float2 c0 = up2(acc[i][0]);
        float2 c1 = up2(acc[i][1]);
        float4 o = {c0.x, c0.y, c1.x, c1.y};
        *(float4*)&S[((size_t)(i0 + ty * 4 + i) * B_ + b) * (size_t)L_ + l0 + tx * 4] = o;
    }
}

// ---------------- row softmax over 1024 ------------------------------------
__global__ __launch_bounds__(256)
void softmax_k(float* __restrict__ S)
{
    __shared__ float redm[8];
    __shared__ float reds[8];
    const size_t row = blockIdx.x;
    float* p = S + row * (size_t)L_;
    const int t = threadIdx.x, lane = t & 31, wid = t >> 5;

    float4 x = *(float4*)&p[t * 4];
    float m = fmaxf(fmaxf(x.x, x.y), fmaxf(x.z, x.w));
    #pragma unroll
    for (int o = 16; o; o >>= 1) m = fmaxf(m, __shfl_xor_sync(~0u, m, o));
    if (lane == 0) redm[wid] = m;
    __syncthreads();
    if (wid == 0) {
        float mm = (lane < 8) ? redm[lane] : -1e30f;
        #pragma unroll
        for (int o = 4; o; o >>= 1) mm = fmaxf(mm, __shfl_xor_sync(~0u, mm, o));
        if (lane == 0) redm[0] = mm;
    }
    __syncthreads();
    m = redm[0];

    float4 e;
    e.x = __expf(x.x - m); e.y = __expf(x.y - m);
    e.z = __expf(x.z - m); e.w = __expf(x.w - m);
    float s = e.x + e.y + e.z + e.w;
    #pragma unroll
    for (int o = 16; o; o >>= 1) s += __shfl_xor_sync(~0u, s, o);
    if (lane == 0) reds[wid] = s;
    __syncthreads();
    if (wid == 0) {
        float ss = (lane < 8) ? reds[lane] : 0.f;
        #pragma unroll
        for (int o = 4; o; o >>= 1) ss += __shfl_xor_sync(~0u, ss, o);
        if (lane == 0) reds[0] = ss;
    }
    __syncthreads();
    float inv = __fdividef(1.0f, reds[0]);
    e.x *= inv; e.y *= inv; e.z *= inv; e.w *= inv;
    *(float4*)&p[t * 4] = e;
}

// ---------------- recurrence ------------------------------------------------
#define RCTA 128
#define RTHR 128
#define HP   516   // padded row pitch (floats), 16B-aligned

__global__ void reset_bar() { g_bar = 0; }

__global__ __launch_bounds__(RTHR)
void gru_k(const float* __restrict__ h0, const float* __restrict__ gi,
           const float* __restrict__ w_hh, const float* __restrict__ b_hh,
           float* __restrict__ out)
{
    extern __shared__ float sm[];
    float* h_s  = sm;                 // [B_][HP]
    float* w_s  = sm + B_ * HP;       // [12][HP]
    float* gh_p = w_s + 12 * HP;      // [4][12][B_]

    const int c = blockIdx.x, t = threadIdx.x;

    // load this CTA's 12 w_hh rows: gate g, d = c*4 + do  -> j = g*4+do
    for (int idx = t; idx < 12 * 128; idx += RTHR) {
        int j = idx >> 7, kk = (idx & 127) * 4;
        int row = (j >> 2) * D_ + c * 4 + (j & 3);
        *(float4*)&w_s[j * HP + kk] = *(const float4*)&w_hh[(size_t)row * D_ + kk];
    }
    __syncthreads();

    // compute-thread mapping (t < 96): kq 0..3, nq 0..3 (3 j-rows), bq 0..5 (4 b)
    const int kq = t / 24, rem = t % 24, nq = rem / 6, bq = rem % 6;
    const int b0 = bq * 4, j0 = nq * 3, kbase = kq * 128;
    // gate-thread mapping (t < 96): b, dq
    const int gb = t % 24, gdq = t / 24;
    const int gd = c * 4 + gdq;

    for (int i = 0; i < L_; ++i) {
        const float* hp = (i == 0) ? h0 : out + (size_t)(i - 1) * B_ * D_;
        for (int idx = t; idx < B_ * 128; idx += RTHR) {
            int b = idx >> 7, kk = (idx & 127) * 4;
            *(float4*)&h_s[b * HP + kk] = *(const float4*)&hp[(size_t)b * D_ + kk];
        }
        __syncthreads();

        if (t < 96) {
            unsigned long long p0[4], p1[4], p2[4];
            #pragma unroll
            for (int r = 0; r < 4; r++) { p0[r] = 0ull; p1[r] = 0ull; p2[r] = 0ull; }
            for (int kk = kbase; kk < kbase + 128; kk += 4) {
                ulonglong2 w0 = *(const ulonglong2*)&w_s[(j0 + 0) * HP + kk];
                ulonglong2 w1 = *(const ulonglong2*)&w_s[(j0 + 1) * HP + kk];
                ulonglong2 w2 = *(const ulonglong2*)&w_s[(j0 + 2) * HP + kk];
                #pragma unroll
                for (int r = 0; r < 4; r++) {
                    ulonglong2 hv = *(const ulonglong2*)&h_s[(b0 + r) * HP + kk];
                    p0[r] = fma2(hv.x, w0.x, p0[r]);
                    p0[r] = fma2(hv.y, w0.y, p0[r]);
                    p1[r] = fma2(hv.x, w1.x, p1[r]);
                    p1[r] = fma2(hv.y, w1.y, p1[r]);
                    p2[r] = fma2(hv.x, w2.x, p2[r]);
                    p2[r] = fma2(hv.y, w2.y, p2[r]);
                }
            }
            #pragma unroll
            for (int r = 0; r < 4; r++) {
                float2 f0 = up2(p0[r]), f1 = up2(p1[r]), f2 = up2(p2[r]);
                gh_p[(kq * 12 + j0 + 0) * B_ + b0 + r] = f0.x + f0.y;
                gh_p[(kq * 12 + j0 + 1) * B_ + b0 + r] = f1.x + f1.y;
                gh_p[(kq * 12 + j0 + 2) * B_ + b0 + r] = f2.x + f2.y;
            }
        }
        __syncthreads();

        if (t < 96) {
            float ghr = 0.f, ghz = 0.f, ghn = 0.f;
            #pragma unroll
            for (int q = 0; q < 4; q++) {
                ghr += gh_p[(q * 12 + 0 + gdq) * B_ + gb];
                ghz += gh_p[(q * 12 + 4 + gdq) * B_ + gb];
                ghn += gh_p[(q * 12 + 8 + gdq) * B_ + gb];
            }
            size_t girow = ((size_t)i * B_ + gb) * TD;
            float ir = gi[girow + gd];
            float iz = gi[girow + D_ + gd];
            float in = gi[girow + 2 * D_ + gd];
            float hr = ghr + b_hh[gd];
            float hz = ghz + b_hh[D_ + gd];
            float hn = ghn + b_hh[2 * D_ + gd];
            float r = __fdividef(1.0f, 1.0f + __expf(-(ir + hr)));
            float z = __fdividef(1.0f, 1.0f + __expf(-(iz + hz)));
            float n = tanhf(in + r * hn);
            float hprev = h_s[gb * HP + gd];
            float hnew = (1.0f - z) * n + z * hprev;
            out[((size_t)i * B_ + gb) * D_ + gd] = hnew;
        }

        // global step barrier (monotonic counter, reset by reset_bar each launch)
        __threadfence();
        __syncthreads();
        if (t == 0) {
            atomicAdd(&g_bar, 1u);
            unsigned tgt = (unsigned)(i + 1) * gridDim.x;
            while (*((volatile unsigned*)&g_bar) < tgt) { }
        }
        __syncthreads();
        __threadfence();
    }
}

// ---------------- launch -----------------------------------------------------
extern "C" void kernel_launch(void* const* d_in, const int* in_sizes, int n_in,
                              void* d_out, int out_size)
{
    const float* v    = (const float*)d_in[0];
    const float* h0   = (const float*)d_in[1];
    const float* V    = (const float*)d_in[2];
    const float* Wp   = (const float*)d_in[3];
    const float* Wp_  = (const float*)d_in[4];
    const float* w_ih = (const float*)d_in[5];
    const float* w_hh = (const float*)d_in[6];
    const float* b_ih = (const float*)d_in[7];
    const float* b_hh = (const float*)d_in[8];
    float* out = (float*)d_out;

    float *ta, *tb, *S, *c, *gi;
    cudaGetSymbolAddress((void**)&ta, g_ta);
    cudaGetSymbolAddress((void**)&tb, g_tb);
    cudaGetSymbolAddress((void**)&S,  g_S);
    cudaGetSymbolAddress((void**)&c,  g_c);
    cudaGetSymbolAddress((void**)&gi, g_gi);

    const int smem_gru = (B_ * HP + 12 * HP + 4 * 12 * B_) * 4;
    cudaFuncSetAttribute(gru_k, cudaFuncAttributeMaxDynamicSharedMemorySize, smem_gru);

    // 1,2: projections with tanh epilogue (M=24576, N=512, K=512)
    sgemm2<true, false, true><<<dim3(D_ / 128, (L_ * B_) / 128, 1), 256>>>(
        v, D_, 0, Wp, D_, 0, nullptr, ta, D_, 0, D_);
    sgemm2<true, false, true><<<dim3(D_ / 128, (L_ * B_) / 128, 1), 256>>>(
        v, D_, 0, Wp_, D_, 0, nullptr, tb, D_, 0, D_);

    // 3: attention scores
    scores_k<<<dim3(L_ / 64, L_ / 64, B_), 256>>>(ta, tb, V, S);

    // 4: softmax over l
    softmax_k<<<L_ * B_, 256>>>(S);

    // 5: context c[i,b,:] = sum_l a[i,b,l] * v[l,b,:]  (per-b NN GEMM)
    sgemm2<false, false, false><<<dim3(D_ / 128, L_ / 128, B_), 256>>>(
        S, (long)B_ * L_, L_,
        v, (long)B_ * D_, D_,
        nullptr,
        c, (long)B_ * D_, D_,
        L_);

    // 6: gi = c @ w_ih^T + b_ih  (M=24576, N=1536, K=512)
    sgemm2<true, true, false><<<dim3(TD / 128, (L_ * B_) / 128, 1), 256>>>(
        c, D_, 0, w_ih, D_, 0, b_ih, gi, TD, 0, D_);

    // 7: recurrence
    reset_bar<<<1, 1>>>();
    gru_k<<<RCTA, RTHR, smem_gru>>>(h0, gi, w_hh, b_hh, out);
}